// round 4
// baseline (speedup 1.0000x reference)
#include <cuda_runtime.h>

#define NC 128
#define EPS 1e-5f
#define RAYS_PER_CTA 8          // 8 warps/CTA, one ray per warp
#define THREADS (RAYS_PER_CTA * 32)

__global__ __launch_bounds__(THREADS) void pdf_sampler_kernel(
    const float* __restrict__ deltas,
    const float* __restrict__ density,
    const float* __restrict__ bins,
    const float* __restrict__ u,
    float* __restrict__ out)
{
    const int lane = threadIdx.x & 31;
    const int wrp  = threadIdx.x >> 5;
    const int ray  = blockIdx.x * RAYS_PER_CTA + wrp;

    // Eytzinger tree of cdf[1..127] (ranks 0..126 of cd1), slot 127 = dummy
    __shared__ float eytz[RAYS_PER_CTA][NC];
    // bins[0..128], row padded to 132 floats so every row is 16B-aligned
    __shared__ __align__(16) float bins_sh[RAYS_PER_CTA][132];

    const size_t base_c = (size_t)ray * NC;

    // ---- coalesced loads (bins array itself is NOT loaded; only near) ----
    const float4 dv = *(const float4*)(deltas  + base_c + 4 * lane);
    const float4 rv = *(const float4*)(density + base_c + 4 * lane);
    const float4 uv = *(const float4*)(u       + base_c + 4 * lane);
    const float nearv = bins[(size_t)ray * (NC + 1)];   // warp-uniform load

    // ---- per-lane serial prefixes: dd = delta*density, and delta itself ----
    const float dd0 = dv.x * rv.x;
    const float dd1 = dv.y * rv.y;
    const float dd2 = dv.z * rv.z;
    const float dd3 = dv.w * rv.w;
    const float pA0 = dd0, pA1 = pA0 + dd1, pA2 = pA1 + dd2, pA3 = pA2 + dd3;
    const float pD0 = dv.x, pD1 = pD0 + dv.y, pD2 = pD1 + dv.z, pD3 = pD2 + dv.w;

    // ---- fused dual warp scan (dd totals + delta totals) ----
    float sA = pA3, sD = pD3;
    #pragma unroll
    for (int o = 1; o < 32; o <<= 1) {
        const float nA = __shfl_up_sync(0xffffffffu, sA, o);
        const float nD = __shfl_up_sync(0xffffffffu, sD, o);
        if (lane >= o) { sA += nA; sD += nD; }
    }
    const float offA = sA - pA3;      // exclusive dd-cumsum at element e
    const float offD = sD - pD3;      // exclusive delta-cumsum at element e

    // ---- telescoped cdf: cumsum(w)[i] = 1 - exp(-cumsum(dd)[i]) ----
    const float total = __shfl_sync(0xffffffffu, sA, 31);
    const float wsum  = 1.0f - __expf(-total);
    const float pad   = fmaxf(EPS - wsum, 0.0f);
    const float inv   = 1.0f / (wsum + pad);
    const float ps    = pad * (1.0f / (float)NC);

    const int e = 4 * lane;
    const float cv0 = fminf(1.0f, (1.0f - __expf(-(offA + pA0)) + ps * (float)(e + 1)) * inv);
    const float cv1 = fminf(1.0f, (1.0f - __expf(-(offA + pA1)) + ps * (float)(e + 2)) * inv);
    const float cv2 = fminf(1.0f, (1.0f - __expf(-(offA + pA2)) + ps * (float)(e + 3)) * inv);
    const float cv3 = fminf(1.0f, (1.0f - __expf(-(offA + pA3)) + ps * (float)(e + 4)) * inv);

    const float cdlast = __shfl_sync(0xffffffffu, cv3, 31);   // cdf[128]

    // ---- reconstruct bins[e..e+4] in registers; write via one STS.128 ----
    const float be0 = nearv + offD;          // bins[e]
    const float be1 = nearv + offD + pD0;
    const float be2 = nearv + offD + pD1;
    const float be3 = nearv + offD + pD2;
    const float be4 = nearv + offD + pD3;    // bins[e+4]
    *(float4*)(&bins_sh[wrp][e]) = make_float4(be0, be1, be2, be3);  // conflict-free
    if (lane == 31) bins_sh[wrp][NC] = be4;  // bins[128]

    // ---- scatter cdf[1..128] (=cd1 ranks e..e+3) into Eytzinger layout ----
    {
        const float vals[4] = {cv0, cv1, cv2, cv3};
        #pragma unroll
        for (int j = 0; j < 4; j++) {
            const int r = e + j;                 // rank in cd1
            const int t = r + 1;
            const int k = __ffs(t) - 1;          // trailing zeros
            const int kc = (k > 6) ? 6 : k;
            int p = (1 << (6 - kc)) - 1 + (t >> (kc + 1));
            p = (r == 127) ? 127 : p;            // rank 127 -> dummy slot
            eytz[wrp][p] = vals[j];
        }
    }

    __syncwarp();

    // ---- per-sample inverse CDF via Eytzinger descent ----
    const float* __restrict__ cd = eytz[wrp];
    const float* __restrict__ bn = bins_sh[wrp];
    float4 res;

    #pragma unroll
    for (int i = 0; i < 4; i++) {
        const float uu = (i == 0) ? uv.x : (i == 1) ? uv.y : (i == 2) ? uv.z : uv.w;

        int j = 0;
        float c0 = 0.0f;        // predecessor: last probe <= u   (cdf[cnt])
        float c1 = cdlast;      // successor:   last probe  > u   (cdf[cnt+1])
        #pragma unroll
        for (int lvl = 0; lvl < 7; lvl++) {
            const float tv = cd[j];
            const bool p = (tv <= uu);
            c0 = p ? tv : c0;
            c1 = p ? c1 : tv;
            j = 2 * j + 1 + (p ? 1 : 0);
        }
        int cnt = j - 127;                       // #{cdf[1..127] <= u}, in [0,127]
        const bool ex = (cnt == 127) && (cdlast <= uu);
        cnt += ex ? 1 : 0;                       // full count over cdf[1..128]
        c0 = ex ? cdlast : c0;

        // below = cnt, above = min(cnt+1, 128)
        const float b0 = bn[cnt];                // cnt <= 128
        const float b1 = bn[(cnt < NC) ? (cnt + 1) : NC];

        float den = c1 - c0;
        den = (den < EPS) ? 1.0f : den;
        const float frac = __fdividef(uu - c0, den);
        const float s = b0 + frac * (b1 - b0);
        if (i == 0) res.x = s; else if (i == 1) res.y = s; else if (i == 2) res.z = s; else res.w = s;
    }

    *(float4*)(out + base_c + 4 * lane) = res;
}

extern "C" void kernel_launch(void* const* d_in, const int* in_sizes, int n_in,
                              void* d_out, int out_size) {
    const float* deltas  = (const float*)d_in[0];
    const float* density = (const float*)d_in[1];
    const float* bins    = (const float*)d_in[2];
    const float* u       = (const float*)d_in[3];
    float* out = (float*)d_out;

    int R = in_sizes[0] / NC;               // 131072
    pdf_sampler_kernel<<<R / RAYS_PER_CTA, THREADS>>>(deltas, density, bins, u, out);
}

// round 5
// speedup vs baseline: 1.1474x; 1.1474x over previous
#include <cuda_runtime.h>

#define NC 128
#define EPS 1e-5f
#define RAYS_PER_CTA 8          // 8 warps/CTA, one ray per warp
#define THREADS (RAYS_PER_CTA * 32)

__global__ __launch_bounds__(THREADS) void pdf_sampler_kernel(
    const float* __restrict__ deltas,
    const float* __restrict__ density,
    const float* __restrict__ bins,
    const float* __restrict__ u,
    float* __restrict__ out)
{
    const int lane = threadIdx.x & 31;
    const int wrp  = threadIdx.x >> 5;
    const int ray  = blockIdx.x * RAYS_PER_CTA + wrp;

    __shared__ __align__(16) float cdfv_sh[RAYS_PER_CTA][NC];   // cdf[1..128]
    __shared__ __align__(16) float bins_sh[RAYS_PER_CTA][132];  // bins[0..128], padded row

    const size_t base_c = (size_t)ray * NC;

    // ---- coalesced loads (full bins row NOT loaded; only near) ----
    const float4 dv = *(const float4*)(deltas  + base_c + 4 * lane);
    const float4 rv = *(const float4*)(density + base_c + 4 * lane);
    const float4 uv = *(const float4*)(u       + base_c + 4 * lane);
    const float nearv = bins[(size_t)ray * (NC + 1)];   // warp-uniform

    // ---- per-lane serial prefixes: dd = delta*density, and delta ----
    const float dd0 = dv.x * rv.x;
    const float dd1 = dv.y * rv.y;
    const float dd2 = dv.z * rv.z;
    const float dd3 = dv.w * rv.w;
    const float pA0 = dd0, pA1 = pA0 + dd1, pA2 = pA1 + dd2, pA3 = pA2 + dd3;
    const float pD0 = dv.x, pD1 = pD0 + dv.y, pD2 = pD1 + dv.z, pD3 = pD2 + dv.w;

    // ---- fused dual warp scan over lane totals ----
    float sA = pA3, sD = pD3;
    #pragma unroll
    for (int o = 1; o < 32; o <<= 1) {
        const float nA = __shfl_up_sync(0xffffffffu, sA, o);
        const float nD = __shfl_up_sync(0xffffffffu, sD, o);
        if (lane >= o) { sA += nA; sD += nD; }
    }
    const float offA = sA - pA3;      // exclusive dd-cumsum at element e
    const float offD = sD - pD3;      // exclusive delta-cumsum at element e

    // ---- telescoped cdf: cumsum(w)[i] = 1 - exp(-cumsum(dd)[i]) ----
    const float total = __shfl_sync(0xffffffffu, sA, 31);
    const float wsum  = 1.0f - __expf(-total);
    const float pad   = fmaxf(EPS - wsum, 0.0f);
    const float inv   = __fdividef(1.0f, wsum + pad);
    const float ps    = pad * (1.0f / (float)NC);

    const int e = 4 * lane;
    float4 cv;
    cv.x = fminf(1.0f, (1.0f - __expf(-(offA + pA0)) + ps * (float)(e + 1)) * inv);
    cv.y = fminf(1.0f, (1.0f - __expf(-(offA + pA1)) + ps * (float)(e + 2)) * inv);
    cv.z = fminf(1.0f, (1.0f - __expf(-(offA + pA2)) + ps * (float)(e + 3)) * inv);
    cv.w = fminf(1.0f, (1.0f - __expf(-(offA + pA3)) + ps * (float)(e + 4)) * inv);
    *(float4*)(&cdfv_sh[wrp][e]) = cv;            // aligned, conflict-free

    // ---- reconstruct bins[e..e+4] in registers; one STS.128 ----
    const float be0 = nearv + offD;
    *(float4*)(&bins_sh[wrp][e]) =
        make_float4(be0, be0 + pD0, be0 + pD1, be0 + pD2);
    if (lane == 31) bins_sh[wrp][NC] = be0 + pD3;   // bins[128]

    __syncwarp();

    // ---- per-sample inverse CDF: plain predicated binary search (R2 style) ----
    // cd[i] = cdf[i+1]; pos = #{cd[k] <= u}; below = pos, above = min(pos+1,128)
    const float* __restrict__ cd = cdfv_sh[wrp];
    const float* __restrict__ bn = bins_sh[wrp];
    float4 res;

    #pragma unroll
    for (int i = 0; i < 4; i++) {
        const float uu = (i == 0) ? uv.x : (i == 1) ? uv.y : (i == 2) ? uv.z : uv.w;

        int pos = 0;
        #pragma unroll
        for (int step = 64; step >= 1; step >>= 1) {
            if (cd[pos + step - 1] <= uu) pos += step;
        }
        const float c0 = (pos == 0) ? 0.0f : cd[pos - 1];
        const float c1 = cd[(pos < 127) ? pos : 127];
        const float b0 = bn[pos];
        const float b1 = bn[(pos < NC) ? (pos + 1) : NC];

        float den = c1 - c0;
        den = (den < EPS) ? 1.0f : den;
        const float frac = __fdividef(uu - c0, den);
        const float s = b0 + frac * (b1 - b0);
        if (i == 0) res.x = s; else if (i == 1) res.y = s; else if (i == 2) res.z = s; else res.w = s;
    }

    *(float4*)(out + base_c + 4 * lane) = res;
}

extern "C" void kernel_launch(void* const* d_in, const int* in_sizes, int n_in,
                              void* d_out, int out_size) {
    const float* deltas  = (const float*)d_in[0];
    const float* density = (const float*)d_in[1];
    const float* bins    = (const float*)d_in[2];
    const float* u       = (const float*)d_in[3];
    float* out = (float*)d_out;

    int R = in_sizes[0] / NC;               // 131072
    pdf_sampler_kernel<<<R / RAYS_PER_CTA, THREADS>>>(deltas, density, bins, u, out);
}